// round 13
// baseline (speedup 1.0000x reference)
#include <cuda_runtime.h>
#include <cuda_fp16.h>
#include <cuda_bf16.h>
#include <cstdint>

#define N_NODES 100000
#define N_EDGES 1600000
#define DDIM    128
#define CAP     80          // per-row edge bucket capacity (Poisson(16): P(>80)~1e-20)

#define NBIN_CTAS 128       // dedicated binning CTAs co-scheduled with GEMM CTAs
#define NTILES    ((N_NODES + 127) / 128)   // 782 GEMM tiles

// Scratch: h = dropout(x) @ W   [100000 x 128] fp16 = 25.6 MB (L2-resident)
__device__ __half g_h[(size_t)N_NODES * DDIM];
// Per-row edge counts + padded (val, byte-offset) buckets
__device__ int g_cnt[N_NODES];
__device__ unsigned long long g_edges[(size_t)N_NODES * CAP];

// ---------------------------------------------------------------------------
// JAX threefry2x32 dropout mask, key = PRNGKey(42) = (0, 42), keep_prob = 0.5
// PARTITIONABLE spec: bits = out0 ^ out1 with ctr (0, i).
// keep  <=>  (int)bits >= 0   (bit-exact sign test)
// ---------------------------------------------------------------------------
__device__ __forceinline__ float dropout_apply(float v, unsigned i) {
    const unsigned ks0 = 0u, ks1 = 42u, ks2 = 0u ^ 42u ^ 0x1BD11BDAu;
    unsigned x0 = 0u + ks0;
    unsigned x1 = i + ks1;
#define TF_ROUND(R) { x0 += x1; x1 = __funnelshift_l(x1, x1, (R)); x1 ^= x0; }
    TF_ROUND(13) TF_ROUND(15) TF_ROUND(26) TF_ROUND(6)
    x0 += ks1; x1 += ks2 + 1u;
    TF_ROUND(17) TF_ROUND(29) TF_ROUND(16) TF_ROUND(24)
    x0 += ks2; x1 += ks0 + 2u;
    TF_ROUND(13) TF_ROUND(15) TF_ROUND(26) TF_ROUND(6)
    x0 += ks0; x1 += ks1 + 3u;
    TF_ROUND(17) TF_ROUND(29) TF_ROUND(16) TF_ROUND(24)
    x0 += ks1; x1 += ks2 + 4u;
    TF_ROUND(13) TF_ROUND(15) TF_ROUND(26) TF_ROUND(6)
    x0 += ks2; x1 += ks0 + 5u;
#undef TF_ROUND
    unsigned bits = x0 ^ x1;
    return ((int)bits >= 0) ? (v + v) : 0.0f;
}

// ---------------------------------------------------------------------------
// Heterogeneous kernel (occupancy 3):
//   blockIdx < NBIN_CTAS  : bin COO edges (latency-bound, rides along)
//   blockIdx >= NBIN_CTAS : fused dropout + HMMA GEMM tile (ALU/issue-bound)
// GEMM computes N in two 64-col halves -> acc regs halved -> 3 CTAs/SM.
// ---------------------------------------------------------------------------
#define LDS_H 136   // halves per smem row (128 + 8 pad)

__global__ void __launch_bounds__(256, 3)
gemm_bin_hmma(const float* __restrict__ x, const float* __restrict__ W,
              const int* __restrict__ arow, const int* __restrict__ acol,
              const float* __restrict__ aval) {
    const int tid = threadIdx.x;

    // ================= bin population =================
    if (blockIdx.x < NBIN_CTAS) {
        const int NQ = N_EDGES / 4;
        const int stride = NBIN_CTAS * 256;
        for (int q = blockIdx.x * 256 + tid; q < NQ; q += stride) {
            int4   r4 = *reinterpret_cast<const int4*>(&arow[q * 4]);
            int4   c4 = *reinterpret_cast<const int4*>(&acol[q * 4]);
            float4 v4 = *reinterpret_cast<const float4*>(&aval[q * 4]);
            #pragma unroll
            for (int j = 0; j < 4; j++) {
                int   r = (j == 0) ? r4.x : (j == 1) ? r4.y : (j == 2) ? r4.z : r4.w;
                int   c = (j == 0) ? c4.x : (j == 1) ? c4.y : (j == 2) ? c4.z : c4.w;
                float v = (j == 0) ? v4.x : (j == 1) ? v4.y : (j == 2) ? v4.z : v4.w;
                int slot = atomicAdd(&g_cnt[r], 1);
                if (slot < CAP) {
                    unsigned long long pk =
                        ((unsigned long long)__float_as_uint(v) << 32) |
                        (unsigned)(c << 8);          // byte offset: c*128 halves*2B
                    g_edges[(size_t)r * CAP + slot] = pk;
                }
            }
        }
        return;
    }

    // ================= GEMM population =================
    extern __shared__ __half sm[];
    __half* Ws = sm;                    // [128][LDS_H]
    __half* xs = sm + 128 * LDS_H;      // [128][LDS_H]

    const int rowBase = (blockIdx.x - NBIN_CTAS) * 128;

    // ---- stage W (fp32 -> fp16) ----
    #pragma unroll 4
    for (int idx = tid; idx < 128 * 64; idx += 256) {
        int k = idx >> 6;
        int n = (idx & 63) * 2;
        float2 w2 = *reinterpret_cast<const float2*>(&W[k * 128 + n]);
        *reinterpret_cast<__half2*>(&Ws[k * LDS_H + n]) = __floats2half2_rn(w2.x, w2.y);
    }

    // ---- stage x tile: fused threefry dropout, 4 chains/thread/iter ----
    #pragma unroll 2
    for (int idx = tid; idx < 128 * 32; idx += 256) {
        int r = idx >> 5;
        int k = (idx & 31) * 4;
        int row = rowBase + r;
        float v0 = 0.f, v1 = 0.f, v2 = 0.f, v3 = 0.f;
        if (row < N_NODES) {
            unsigned gi = (unsigned)row * 128u + (unsigned)k;
            float4 xv = *reinterpret_cast<const float4*>(&x[(size_t)row * 128 + k]);
            v0 = dropout_apply(xv.x, gi);
            v1 = dropout_apply(xv.y, gi + 1u);
            v2 = dropout_apply(xv.z, gi + 2u);
            v3 = dropout_apply(xv.w, gi + 3u);
        }
        union { __half2 h[2]; uint2 u; } p;
        p.h[0] = __floats2half2_rn(v0, v1);
        p.h[1] = __floats2half2_rn(v2, v3);
        *reinterpret_cast<uint2*>(&xs[r * LDS_H + k]) = p.u;
    }
    __syncthreads();

    const int wid  = tid >> 5;
    const int lane = tid & 31;
    const int m0   = wid * 16;

    uint32_t xs_base = (uint32_t)__cvta_generic_to_shared(xs);
    uint32_t ws_base = (uint32_t)__cvta_generic_to_shared(Ws);

    const int r_lo = m0 + (lane >> 2);
    const int colq = 2 * (lane & 3);

    // N processed in two 64-col halves: acc regs halved -> occupancy 3
    #pragma unroll
    for (int nh = 0; nh < 2; nh++) {
        const int nbase = nh * 64;

        float acc[8][4];
        #pragma unroll
        for (int t = 0; t < 8; t++)
            #pragma unroll
            for (int c = 0; c < 4; c++)
                acc[t][c] = 0.f;

        #pragma unroll
        for (int k0 = 0; k0 < 128; k0 += 16) {
            int arow_ = m0 + (lane & 15);
            int acol_ = k0 + ((lane & 16) ? 8 : 0);
            uint32_t aaddr = xs_base + (uint32_t)(arow_ * LDS_H + acol_) * 2u;
            uint32_t a0, a1, a2, a3;
            asm volatile("ldmatrix.sync.aligned.m8n8.x4.shared.b16 {%0,%1,%2,%3}, [%4];"
                         : "=r"(a0), "=r"(a1), "=r"(a2), "=r"(a3) : "r"(aaddr));

            #pragma unroll
            for (int np = 0; np < 4; np++) {
                int n0 = nbase + np * 16;
                int brow = k0 + (lane & 15);
                int bcol = n0 + ((lane & 16) ? 8 : 0);
                uint32_t baddr = ws_base + (uint32_t)(brow * LDS_H + bcol) * 2u;
                uint32_t b0, b1, b2, b3;
                asm volatile("ldmatrix.sync.aligned.m8n8.x4.trans.shared.b16 {%0,%1,%2,%3}, [%4];"
                             : "=r"(b0), "=r"(b1), "=r"(b2), "=r"(b3) : "r"(baddr));

                int nt = np * 2;
                asm volatile("mma.sync.aligned.m16n8k16.row.col.f32.f16.f16.f32 "
                             "{%0,%1,%2,%3}, {%4,%5,%6,%7}, {%8,%9}, {%0,%1,%2,%3};"
                             : "+f"(acc[nt][0]), "+f"(acc[nt][1]),
                               "+f"(acc[nt][2]), "+f"(acc[nt][3])
                             : "r"(a0), "r"(a1), "r"(a2), "r"(a3), "r"(b0), "r"(b1));
                asm volatile("mma.sync.aligned.m16n8k16.row.col.f32.f16.f16.f32 "
                             "{%0,%1,%2,%3}, {%4,%5,%6,%7}, {%8,%9}, {%0,%1,%2,%3};"
                             : "+f"(acc[nt+1][0]), "+f"(acc[nt+1][1]),
                               "+f"(acc[nt+1][2]), "+f"(acc[nt+1][3])
                             : "r"(a0), "r"(a1), "r"(a2), "r"(a3), "r"(b2), "r"(b3));
            }
        }

        #pragma unroll
        for (int nt = 0; nt < 8; nt++) {
            int col = nbase + nt * 8 + colq;
            int row0 = rowBase + r_lo;
            int row1 = row0 + 8;
            if (row0 < N_NODES)
                *reinterpret_cast<__half2*>(&g_h[(size_t)row0 * 128 + col]) =
                    __floats2half2_rn(acc[nt][0], acc[nt][1]);
            if (row1 < N_NODES)
                *reinterpret_cast<__half2*>(&g_h[(size_t)row1 * 128 + col]) =
                    __floats2half2_rn(acc[nt][2], acc[nt][3]);
        }
    }
}

// ---------------------------------------------------------------------------
// Gather-SpMM: one warp per row, paired ulonglong2 edge loads, unroll-4.
// Gather address = hbase(lane) + 32-bit pre-scaled offset (no IMAD).
// fp32 register accumulation, fused ReLU, single float4 store.
// ---------------------------------------------------------------------------
__global__ void __launch_bounds__(256)
spmm_row_kernel(float* __restrict__ out) {
    int w = blockIdx.x * 8 + (threadIdx.x >> 5);   // row id
    if (w >= N_NODES) return;
    int lane = threadIdx.x & 31;

    int n = g_cnt[w];
    if (n > CAP) n = CAP;
    const unsigned long long* eb = &g_edges[(size_t)w * CAP];
    const char* hbase = reinterpret_cast<const char*>(g_h) + lane * 8;

    float a0 = 0.f, a1 = 0.f, a2 = 0.f, a3 = 0.f;

    int e = 0;
    for (; e + 3 < n; e += 4) {     // e multiple of 4 -> 32B-aligned pair loads
        ulonglong2 q0 = *reinterpret_cast<const ulonglong2*>(&eb[e]);
        ulonglong2 q1 = *reinterpret_cast<const ulonglong2*>(&eb[e + 2]);
        uint2 g0 = *reinterpret_cast<const uint2*>(hbase + (unsigned)q0.x);
        uint2 g1 = *reinterpret_cast<const uint2*>(hbase + (unsigned)q0.y);
        uint2 g2 = *reinterpret_cast<const uint2*>(hbase + (unsigned)q1.x);
        uint2 g3 = *reinterpret_cast<const uint2*>(hbase + (unsigned)q1.y);
        float v0 = __uint_as_float((unsigned)(q0.x >> 32));
        float v1 = __uint_as_float((unsigned)(q0.y >> 32));
        float v2 = __uint_as_float((unsigned)(q1.x >> 32));
        float v3 = __uint_as_float((unsigned)(q1.y >> 32));
        union { uint2 u; __half2 h[2]; } q;
        q.u = g0; { float2 f0 = __half22float2(q.h[0]), f1 = __half22float2(q.h[1]);
                    a0 += v0 * f0.x; a1 += v0 * f0.y; a2 += v0 * f1.x; a3 += v0 * f1.y; }
        q.u = g1; { float2 f0 = __half22float2(q.h[0]), f1 = __half22float2(q.h[1]);
                    a0 += v1 * f0.x; a1 += v1 * f0.y; a2 += v1 * f1.x; a3 += v1 * f1.y; }
        q.u = g2; { float2 f0 = __half22float2(q.h[0]), f1 = __half22float2(q.h[1]);
                    a0 += v2 * f0.x; a1 += v2 * f0.y; a2 += v2 * f1.x; a3 += v2 * f1.y; }
        q.u = g3; { float2 f0 = __half22float2(q.h[0]), f1 = __half22float2(q.h[1]);
                    a0 += v3 * f0.x; a1 += v3 * f0.y; a2 += v3 * f1.x; a3 += v3 * f1.y; }
    }
    for (; e < n; e++) {
        unsigned long long p = __ldg(&eb[e]);
        float v = __uint_as_float((unsigned)(p >> 32));
        uint2 g = *reinterpret_cast<const uint2*>(hbase + (unsigned)p);
        union { uint2 u; __half2 h[2]; } q; q.u = g;
        float2 f0 = __half22float2(q.h[0]);
        float2 f1 = __half22float2(q.h[1]);
        a0 += v * f0.x; a1 += v * f0.y; a2 += v * f1.x; a3 += v * f1.y;
    }

    float4 o = make_float4(fmaxf(a0, 0.f), fmaxf(a1, 0.f),
                           fmaxf(a2, 0.f), fmaxf(a3, 0.f));
    *reinterpret_cast<float4*>(&out[(size_t)w * 128 + lane * 4]) = o;
}

// ---------------------------------------------------------------------------
extern "C" void kernel_launch(void* const* d_in, const int* in_sizes, int n_in,
                              void* d_out, int out_size) {
    const float* x    = (const float*)d_in[0];   // [100000, 128]
    const float* W    = (const float*)d_in[1];   // [128, 128]
    const int*   arow = (const int*)  d_in[2];   // [1600000]
    const int*   acol = (const int*)  d_in[3];   // [1600000]
    const float* aval = (const float*)d_in[4];   // [1600000]
    float* out = (float*)d_out;                  // [100000, 128]

    const int smem = 2 * 128 * LDS_H * (int)sizeof(__half);  // 69632 B
    cudaFuncSetAttribute(gemm_bin_hmma,
                         cudaFuncAttributeMaxDynamicSharedMemorySize, smem);

    // 1) zero per-row counters via memset node (graph-capturable, no alloc)
    void* cnt_ptr = nullptr;
    cudaGetSymbolAddress(&cnt_ptr, g_cnt);
    cudaMemsetAsync(cnt_ptr, 0, N_NODES * sizeof(int));

    // 2) heterogeneous kernel: bin CTAs (low blockIdx) + GEMM CTAs, concurrent
    gemm_bin_hmma<<<NBIN_CTAS + NTILES, 256, smem>>>(x, W, arow, acol, aval);

    // 3) gather-SpMM with fused ReLU
    spmm_row_kernel<<<(N_NODES + 7) / 8, 256>>>(out);
}

// round 15
// speedup vs baseline: 1.0510x; 1.0510x over previous
#include <cuda_runtime.h>
#include <cuda_fp16.h>
#include <cuda_bf16.h>
#include <cstdint>

#define N_NODES 100000
#define N_EDGES 1600000
#define DDIM    128
#define CAP     80          // per-row edge bucket capacity (Poisson(16): P(>80)~1e-20)

#define NBIN_CTAS 128       // dedicated binning CTAs co-scheduled with GEMM CTAs
#define NTILES    ((N_NODES + 127) / 128)   // 782 GEMM tiles

// Scratch: h = dropout(x) @ W   [100000 x 128] fp16 = 25.6 MB (L2-resident)
__device__ __half g_h[(size_t)N_NODES * DDIM];
// Per-row edge counts + padded (val, byte-offset) buckets
__device__ int g_cnt[N_NODES];
__device__ unsigned long long g_edges[(size_t)N_NODES * CAP];

// reinterpret __half2 bits as u32 (no __half2_as_uint intrinsic in this CUDA)
__device__ __forceinline__ uint32_t h2_as_u32(__half2 h) {
    union { __half2 h; uint32_t u; } c; c.h = h; return c.u;
}

// ---------------------------------------------------------------------------
// JAX threefry2x32 dropout mask, key = PRNGKey(42) = (0, 42), keep_prob = 0.5
// PARTITIONABLE spec: bits = out0 ^ out1 with ctr (0, i).
// keep  <=>  (int)bits >= 0   (bit-exact sign test)
// ---------------------------------------------------------------------------
__device__ __forceinline__ float dropout_apply(float v, unsigned i) {
    const unsigned ks0 = 0u, ks1 = 42u, ks2 = 0u ^ 42u ^ 0x1BD11BDAu;
    unsigned x0 = 0u + ks0;
    unsigned x1 = i + ks1;
#define TF_ROUND(R) { x0 += x1; x1 = __funnelshift_l(x1, x1, (R)); x1 ^= x0; }
    TF_ROUND(13) TF_ROUND(15) TF_ROUND(26) TF_ROUND(6)
    x0 += ks1; x1 += ks2 + 1u;
    TF_ROUND(17) TF_ROUND(29) TF_ROUND(16) TF_ROUND(24)
    x0 += ks2; x1 += ks0 + 2u;
    TF_ROUND(13) TF_ROUND(15) TF_ROUND(26) TF_ROUND(6)
    x0 += ks0; x1 += ks1 + 3u;
    TF_ROUND(17) TF_ROUND(29) TF_ROUND(16) TF_ROUND(24)
    x0 += ks1; x1 += ks2 + 4u;
    TF_ROUND(13) TF_ROUND(15) TF_ROUND(26) TF_ROUND(6)
    x0 += ks2; x1 += ks0 + 5u;
#undef TF_ROUND
    unsigned bits = x0 ^ x1;
    return ((int)bits >= 0) ? (v + v) : 0.0f;
}

// ---------------------------------------------------------------------------
// Heterogeneous kernel (occupancy 2):
//   blockIdx < NBIN_CTAS  : bin COO edges (latency-bound, rides along)
//   blockIdx >= NBIN_CTAS : dropout-direct-to-fragment + HMMA GEMM tile
// A fragments are computed in registers (threefry on the fly) -- no xs smem,
// no A ldmatrix, no staging sync. Only W lives in smem.
// ---------------------------------------------------------------------------
#define LDS_H 136   // halves per smem row (128 + 8 pad)

__global__ void __launch_bounds__(256, 2)
gemm_bin_hmma(const float* __restrict__ x, const float* __restrict__ W,
              const int* __restrict__ arow, const int* __restrict__ acol,
              const float* __restrict__ aval) {
    const int tid = threadIdx.x;

    // ================= bin population =================
    if (blockIdx.x < NBIN_CTAS) {
        const int NQ = N_EDGES / 4;
        const int stride = NBIN_CTAS * 256;
        for (int q = blockIdx.x * 256 + tid; q < NQ; q += stride) {
            int4   r4 = *reinterpret_cast<const int4*>(&arow[q * 4]);
            int4   c4 = *reinterpret_cast<const int4*>(&acol[q * 4]);
            float4 v4 = *reinterpret_cast<const float4*>(&aval[q * 4]);
            #pragma unroll
            for (int j = 0; j < 4; j++) {
                int   r = (j == 0) ? r4.x : (j == 1) ? r4.y : (j == 2) ? r4.z : r4.w;
                int   c = (j == 0) ? c4.x : (j == 1) ? c4.y : (j == 2) ? c4.z : c4.w;
                float v = (j == 0) ? v4.x : (j == 1) ? v4.y : (j == 2) ? v4.z : v4.w;
                int slot = atomicAdd(&g_cnt[r], 1);
                if (slot < CAP) {
                    unsigned long long pk =
                        ((unsigned long long)__float_as_uint(v) << 32) |
                        (unsigned)(c << 8);          // byte offset: c*128 halves*2B
                    g_edges[(size_t)r * CAP + slot] = pk;
                }
            }
        }
        return;
    }

    // ================= GEMM population =================
    extern __shared__ __half sm[];
    __half* Ws = sm;                    // [128][LDS_H]

    const int rowBase = (blockIdx.x - NBIN_CTAS) * 128;

    // ---- stage W (fp32 -> fp16) ----
    #pragma unroll 4
    for (int idx = tid; idx < 128 * 64; idx += 256) {
        int k = idx >> 6;
        int n = (idx & 63) * 2;
        float2 w2 = *reinterpret_cast<const float2*>(&W[k * 128 + n]);
        *reinterpret_cast<__half2*>(&Ws[k * LDS_H + n]) = __floats2half2_rn(w2.x, w2.y);
    }
    __syncthreads();

    const int wid  = tid >> 5;
    const int lane = tid & 31;
    const int m0   = wid * 16;

    uint32_t ws_base = (uint32_t)__cvta_generic_to_shared(Ws);

    // A-fragment ownership for mma.m16n8k16 (row-major A):
    //   rows r0 = m0 + lane/4, r1 = r0 + 8
    //   cols kc = k0 + (lane%4)*2 (+1), and kc+8 (+9)
    const int r_lo  = m0 + (lane >> 2);
    const int row0g = rowBase + r_lo;        // global row for a0/a2
    const int row1g = row0g + 8;             // global row for a1/a3
    const bool ok0 = (row0g < N_NODES);
    const bool ok1 = (row1g < N_NODES);
    const float* xr0 = &x[(size_t)row0g * 128];
    const float* xr1 = &x[(size_t)row1g * 128];
    const unsigned base0 = (unsigned)row0g * 128u;
    const unsigned base1 = (unsigned)row1g * 128u;
    const int kq = (lane & 3) * 2;

    float acc[16][4];
    #pragma unroll
    for (int t = 0; t < 16; t++)
        #pragma unroll
        for (int c = 0; c < 4; c++)
            acc[t][c] = 0.f;

    #pragma unroll
    for (int k0 = 0; k0 < 128; k0 += 16) {
        const int kc = k0 + kq;

        // load 4x float2 (issue all before ciphers), guard OOB rows
        float2 xa = ok0 ? *reinterpret_cast<const float2*>(&xr0[kc])
                        : make_float2(0.f, 0.f);
        float2 xb = ok1 ? *reinterpret_cast<const float2*>(&xr1[kc])
                        : make_float2(0.f, 0.f);
        float2 xc = ok0 ? *reinterpret_cast<const float2*>(&xr0[kc + 8])
                        : make_float2(0.f, 0.f);
        float2 xd = ok1 ? *reinterpret_cast<const float2*>(&xr1[kc + 8])
                        : make_float2(0.f, 0.f);

        // 8 independent threefry chains -> A fragment registers
        unsigned i0 = base0 + (unsigned)kc;
        unsigned i1 = base1 + (unsigned)kc;
        uint32_t a0 = h2_as_u32(__floats2half2_rn(dropout_apply(xa.x, i0),
                                                  dropout_apply(xa.y, i0 + 1u)));
        uint32_t a1 = h2_as_u32(__floats2half2_rn(dropout_apply(xb.x, i1),
                                                  dropout_apply(xb.y, i1 + 1u)));
        uint32_t a2 = h2_as_u32(__floats2half2_rn(dropout_apply(xc.x, i0 + 8u),
                                                  dropout_apply(xc.y, i0 + 9u)));
        uint32_t a3 = h2_as_u32(__floats2half2_rn(dropout_apply(xd.x, i1 + 8u),
                                                  dropout_apply(xd.y, i1 + 9u)));

        #pragma unroll
        for (int np = 0; np < 8; np++) {
            int n0 = np * 16;
            int brow = k0 + (lane & 15);
            int bcol = n0 + ((lane & 16) ? 8 : 0);
            uint32_t baddr = ws_base + (uint32_t)(brow * LDS_H + bcol) * 2u;
            uint32_t b0, b1, b2, b3;
            asm volatile("ldmatrix.sync.aligned.m8n8.x4.trans.shared.b16 {%0,%1,%2,%3}, [%4];"
                         : "=r"(b0), "=r"(b1), "=r"(b2), "=r"(b3) : "r"(baddr));

            int nt = np * 2;
            asm volatile("mma.sync.aligned.m16n8k16.row.col.f32.f16.f16.f32 "
                         "{%0,%1,%2,%3}, {%4,%5,%6,%7}, {%8,%9}, {%0,%1,%2,%3};"
                         : "+f"(acc[nt][0]), "+f"(acc[nt][1]),
                           "+f"(acc[nt][2]), "+f"(acc[nt][3])
                         : "r"(a0), "r"(a1), "r"(a2), "r"(a3), "r"(b0), "r"(b1));
            asm volatile("mma.sync.aligned.m16n8k16.row.col.f32.f16.f16.f32 "
                         "{%0,%1,%2,%3}, {%4,%5,%6,%7}, {%8,%9}, {%0,%1,%2,%3};"
                         : "+f"(acc[nt+1][0]), "+f"(acc[nt+1][1]),
                           "+f"(acc[nt+1][2]), "+f"(acc[nt+1][3])
                         : "r"(a0), "r"(a1), "r"(a2), "r"(a3), "r"(b2), "r"(b3));
        }
    }

    const int colq = 2 * (lane & 3);
    #pragma unroll
    for (int nt = 0; nt < 16; nt++) {
        int col = nt * 8 + colq;
        if (ok0)
            *reinterpret_cast<__half2*>(&g_h[(size_t)row0g * 128 + col]) =
                __floats2half2_rn(acc[nt][0], acc[nt][1]);
        if (ok1)
            *reinterpret_cast<__half2*>(&g_h[(size_t)row1g * 128 + col]) =
                __floats2half2_rn(acc[nt][2], acc[nt][3]);
    }
}

// ---------------------------------------------------------------------------
// Gather-SpMM: one warp per row, paired ulonglong2 edge loads, unroll-4.
// Gather address = hbase(lane) + 32-bit pre-scaled offset (no IMAD).
// fp32 register accumulation, fused ReLU, single float4 store.
// ---------------------------------------------------------------------------
__global__ void __launch_bounds__(256)
spmm_row_kernel(float* __restrict__ out) {
    int w = blockIdx.x * 8 + (threadIdx.x >> 5);   // row id
    if (w >= N_NODES) return;
    int lane = threadIdx.x & 31;

    int n = g_cnt[w];
    if (n > CAP) n = CAP;
    const unsigned long long* eb = &g_edges[(size_t)w * CAP];
    const char* hbase = reinterpret_cast<const char*>(g_h) + lane * 8;

    float a0 = 0.f, a1 = 0.f, a2 = 0.f, a3 = 0.f;

    int e = 0;
    for (; e + 3 < n; e += 4) {     // e multiple of 4 -> 32B-aligned pair loads
        ulonglong2 q0 = *reinterpret_cast<const ulonglong2*>(&eb[e]);
        ulonglong2 q1 = *reinterpret_cast<const ulonglong2*>(&eb[e + 2]);
        uint2 g0 = *reinterpret_cast<const uint2*>(hbase + (unsigned)q0.x);
        uint2 g1 = *reinterpret_cast<const uint2*>(hbase + (unsigned)q0.y);
        uint2 g2 = *reinterpret_cast<const uint2*>(hbase + (unsigned)q1.x);
        uint2 g3 = *reinterpret_cast<const uint2*>(hbase + (unsigned)q1.y);
        float v0 = __uint_as_float((unsigned)(q0.x >> 32));
        float v1 = __uint_as_float((unsigned)(q0.y >> 32));
        float v2 = __uint_as_float((unsigned)(q1.x >> 32));
        float v3 = __uint_as_float((unsigned)(q1.y >> 32));
        union { uint2 u; __half2 h[2]; } q;
        q.u = g0; { float2 f0 = __half22float2(q.h[0]), f1 = __half22float2(q.h[1]);
                    a0 += v0 * f0.x; a1 += v0 * f0.y; a2 += v0 * f1.x; a3 += v0 * f1.y; }
        q.u = g1; { float2 f0 = __half22float2(q.h[0]), f1 = __half22float2(q.h[1]);
                    a0 += v1 * f0.x; a1 += v1 * f0.y; a2 += v1 * f1.x; a3 += v1 * f1.y; }
        q.u = g2; { float2 f0 = __half22float2(q.h[0]), f1 = __half22float2(q.h[1]);
                    a0 += v2 * f0.x; a1 += v2 * f0.y; a2 += v2 * f1.x; a3 += v2 * f1.y; }
        q.u = g3; { float2 f0 = __half22float2(q.h[0]), f1 = __half22float2(q.h[1]);
                    a0 += v3 * f0.x; a1 += v3 * f0.y; a2 += v3 * f1.x; a3 += v3 * f1.y; }
    }
    for (; e < n; e++) {
        unsigned long long p = __ldg(&eb[e]);
        float v = __uint_as_float((unsigned)(p >> 32));
        uint2 g = *reinterpret_cast<const uint2*>(hbase + (unsigned)p);
        union { uint2 u; __half2 h[2]; } q; q.u = g;
        float2 f0 = __half22float2(q.h[0]);
        float2 f1 = __half22float2(q.h[1]);
        a0 += v * f0.x; a1 += v * f0.y; a2 += v * f1.x; a3 += v * f1.y;
    }

    float4 o = make_float4(fmaxf(a0, 0.f), fmaxf(a1, 0.f),
                           fmaxf(a2, 0.f), fmaxf(a3, 0.f));
    *reinterpret_cast<float4*>(&out[(size_t)w * 128 + lane * 4]) = o;
}

// ---------------------------------------------------------------------------
extern "C" void kernel_launch(void* const* d_in, const int* in_sizes, int n_in,
                              void* d_out, int out_size) {
    const float* x    = (const float*)d_in[0];   // [100000, 128]
    const float* W    = (const float*)d_in[1];   // [128, 128]
    const int*   arow = (const int*)  d_in[2];   // [1600000]
    const int*   acol = (const int*)  d_in[3];   // [1600000]
    const float* aval = (const float*)d_in[4];   // [1600000]
    float* out = (float*)d_out;                  // [100000, 128]

    const int smem = 128 * LDS_H * (int)sizeof(__half);  // 34816 B (W only)
    cudaFuncSetAttribute(gemm_bin_hmma,
                         cudaFuncAttributeMaxDynamicSharedMemorySize, smem);

    // 1) zero per-row counters via memset node (graph-capturable, no alloc)
    void* cnt_ptr = nullptr;
    cudaGetSymbolAddress(&cnt_ptr, g_cnt);
    cudaMemsetAsync(cnt_ptr, 0, N_NODES * sizeof(int));

    // 2) heterogeneous kernel: bin CTAs (low blockIdx) + GEMM CTAs, concurrent
    gemm_bin_hmma<<<NBIN_CTAS + NTILES, 256, smem>>>(x, W, arow, acol, aval);

    // 3) gather-SpMM with fused ReLU
    spmm_row_kernel<<<(N_NODES + 7) / 8, 256>>>(out);
}